// round 1
// baseline (speedup 1.0000x reference)
#include <cuda_runtime.h>
#include <math.h>

#define M_ROWS 8192
#define DMODEL 1024
#define DINNER 4096
#define LSEQ   1024
#define NHEAD  16

// scratch (static device allocations are allowed; cudaMalloc is not)
__device__ float g_Q [M_ROWS*DMODEL];
__device__ float g_K [M_ROWS*DMODEL];
__device__ float g_V [M_ROWS*DMODEL];
__device__ float g_AO[M_ROWS*DMODEL];
__device__ float g_T0[M_ROWS*DMODEL];
__device__ float g_X1[M_ROWS*DMODEL];
__device__ float g_H [M_ROWS*DINNER];

// ---------------------------------------------------------------------------
// GEMM: C[M,N] = A[M,K] @ W[K,N] + bias (+ res) (optional relu). M = 8192.
// 128x128 block tile, K-tile 16, 256 threads, 8x8 micro-tile (split 4+4).
// ---------------------------------------------------------------------------
__global__ __launch_bounds__(256, 2)
void gemm_kernel(const float* __restrict__ A, const float* __restrict__ W,
                 const float* __restrict__ bias, const float* __restrict__ res,
                 float* __restrict__ C, int N, int K, int relu)
{
    __shared__ float As[2][128 * 17];
    __shared__ float Bs[2][16 * 128];

    const int tid = threadIdx.x;
    const int tx = tid & 15, ty = tid >> 4;
    const int bm = blockIdx.y * 128, bn = blockIdx.x * 128;

    const int ar  = tid >> 2;           // 0..63
    const int ac4 = (tid & 3) << 2;     // 0,4,8,12
    const int br  = tid >> 5;           // 0..7
    const int bc  = (tid & 31) << 2;    // 0..124

    const float* Ap0 = A + (size_t)(bm + ar) * K + ac4;
    const float* Ap1 = A + (size_t)(bm + ar + 64) * K + ac4;
    const float* Wp0 = W + (size_t)br * N + bn + bc;
    const float* Wp1 = W + (size_t)(br + 8) * N + bn + bc;

    float4 a0 = *(const float4*)(Ap0);
    float4 a1 = *(const float4*)(Ap1);
    float4 b0 = *(const float4*)(Wp0);
    float4 b1 = *(const float4*)(Wp1);

    {
        float* as = As[0];
        as[ar*17 + ac4+0] = a0.x; as[ar*17 + ac4+1] = a0.y;
        as[ar*17 + ac4+2] = a0.z; as[ar*17 + ac4+3] = a0.w;
        as[(ar+64)*17 + ac4+0] = a1.x; as[(ar+64)*17 + ac4+1] = a1.y;
        as[(ar+64)*17 + ac4+2] = a1.z; as[(ar+64)*17 + ac4+3] = a1.w;
        *(float4*)&Bs[0][br*128 + bc]       = b0;
        *(float4*)&Bs[0][(br+8)*128 + bc]   = b1;
    }
    __syncthreads();

    float acc[8][8];
    #pragma unroll
    for (int i = 0; i < 8; i++)
        #pragma unroll
        for (int j = 0; j < 8; j++) acc[i][j] = 0.f;

    const int NT = K >> 4;
    for (int kt = 0; kt < NT; kt++) {
        const int cur = kt & 1;
        if (kt + 1 < NT) {
            const int k0 = (kt + 1) << 4;
            a0 = *(const float4*)(Ap0 + k0);
            a1 = *(const float4*)(Ap1 + k0);
            b0 = *(const float4*)(Wp0 + (size_t)k0 * N);
            b1 = *(const float4*)(Wp1 + (size_t)k0 * N);
        }
        const float* as = As[cur];
        const float* bs = Bs[cur];
        #pragma unroll
        for (int kk = 0; kk < 16; kk++) {
            float av[8], bv[8];
            #pragma unroll
            for (int i = 0; i < 4; i++) {
                av[i]   = as[(ty*4 + i) * 17 + kk];
                av[i+4] = as[(ty*4 + i + 64) * 17 + kk];
            }
            float4 t0 = *(const float4*)&bs[kk*128 + tx*4];
            float4 t1 = *(const float4*)&bs[kk*128 + 64 + tx*4];
            bv[0]=t0.x; bv[1]=t0.y; bv[2]=t0.z; bv[3]=t0.w;
            bv[4]=t1.x; bv[5]=t1.y; bv[6]=t1.z; bv[7]=t1.w;
            #pragma unroll
            for (int i = 0; i < 8; i++)
                #pragma unroll
                for (int j = 0; j < 8; j++)
                    acc[i][j] += av[i] * bv[j];
        }
        if (kt + 1 < NT) {
            float* as2 = As[cur ^ 1];
            as2[ar*17 + ac4+0] = a0.x; as2[ar*17 + ac4+1] = a0.y;
            as2[ar*17 + ac4+2] = a0.z; as2[ar*17 + ac4+3] = a0.w;
            as2[(ar+64)*17 + ac4+0] = a1.x; as2[(ar+64)*17 + ac4+1] = a1.y;
            as2[(ar+64)*17 + ac4+2] = a1.z; as2[(ar+64)*17 + ac4+3] = a1.w;
            *(float4*)&Bs[cur^1][br*128 + bc]     = b0;
            *(float4*)&Bs[cur^1][(br+8)*128 + bc] = b1;
        }
        __syncthreads();
    }

    // epilogue
    float4 bias0 = *(const float4*)(bias + bn + tx*4);
    float4 bias1 = *(const float4*)(bias + bn + 64 + tx*4);
    float bb[8] = {bias0.x,bias0.y,bias0.z,bias0.w, bias1.x,bias1.y,bias1.z,bias1.w};

    #pragma unroll
    for (int i = 0; i < 8; i++) {
        int row = bm + ((i < 4) ? (ty*4 + i) : (64 + ty*4 + i - 4));
        float* cp = C + (size_t)row * N + bn;
        float4 o0, o1;
        o0.x = acc[i][0] + bb[0]; o0.y = acc[i][1] + bb[1];
        o0.z = acc[i][2] + bb[2]; o0.w = acc[i][3] + bb[3];
        o1.x = acc[i][4] + bb[4]; o1.y = acc[i][5] + bb[5];
        o1.z = acc[i][6] + bb[6]; o1.w = acc[i][7] + bb[7];
        if (res) {
            const float* rp = res + (size_t)row * N + bn;
            float4 r0 = *(const float4*)(rp + tx*4);
            float4 r1 = *(const float4*)(rp + 64 + tx*4);
            o0.x += r0.x; o0.y += r0.y; o0.z += r0.z; o0.w += r0.w;
            o1.x += r1.x; o1.y += r1.y; o1.z += r1.z; o1.w += r1.w;
        }
        if (relu) {
            o0.x = fmaxf(o0.x, 0.f); o0.y = fmaxf(o0.y, 0.f);
            o0.z = fmaxf(o0.z, 0.f); o0.w = fmaxf(o0.w, 0.f);
            o1.x = fmaxf(o1.x, 0.f); o1.y = fmaxf(o1.y, 0.f);
            o1.z = fmaxf(o1.z, 0.f); o1.w = fmaxf(o1.w, 0.f);
        }
        *(float4*)(cp + tx*4)      = o0;
        *(float4*)(cp + 64 + tx*4) = o1;
    }
}

// ---------------------------------------------------------------------------
// Fused relative attention: per (b, h, 64-query tile), online softmax over
// 16 key tiles of 64. rel-k bias via Sq[q][33]; rel-v via bucket accum Tac.
// thread t: rows qa=2*(t>>3), qb=qa+1; key/dim lane sub = t&7 (stride-8 map).
// ---------------------------------------------------------------------------
#define ATTN_SMEM (20864 * 4)

__global__ __launch_bounds__(256, 2)
void attn_kernel(const float* __restrict__ Q, const float* __restrict__ Km,
                 const float* __restrict__ Vm, const float* __restrict__ relk,
                 const float* __restrict__ relv, float* __restrict__ O)
{
    extern __shared__ float smx[];
    float* Qs  = smx;             // [64][65]
    float* Ks  = smx + 4160;      // [64][65]
    float* Vs  = smx + 8320;      // [64][65]
    float* Ps  = smx + 12480;     // [64][65]
    float* Sq  = smx + 16640;     // [64][33]
    float* Tac = smx + 18752;     // [64][33]
    float* Rk  = Ps;              // overlay (used only before main loop)
    float* Rv  = Ks;              // overlay (used only after main loop)

    const int tid = threadIdx.x;
    const int b = blockIdx.z, h = blockIdx.y, qt = blockIdx.x;
    const int q0 = qt << 6;
    const int rp  = tid >> 3;
    const int sub = tid & 7;
    const int qa = rp * 2, qb = qa + 1;

    for (int idx = tid; idx < 1024; idx += 256) {
        int r = idx >> 4, c = (idx & 15) << 2;
        float4 qv = *(const float4*)(Q + (size_t)(b*LSEQ + q0 + r) * DMODEL + h*64 + c);
        Qs[r*65+c] = qv.x; Qs[r*65+c+1] = qv.y; Qs[r*65+c+2] = qv.z; Qs[r*65+c+3] = qv.w;
    }
    for (int idx = tid; idx < 528; idx += 256)
        ((float4*)Rk)[idx] = ((const float4*)relk)[idx];
    for (int idx = tid; idx < 2112; idx += 256) Tac[idx] = 0.f;
    __syncthreads();

    // Sq[q][r] = (Qh[q] . rel_k[r]) / 8
    for (int idx = tid; idx < 2112; idx += 256) {
        int qq = idx / 33, r = idx - qq * 33;
        float s = 0.f;
        #pragma unroll 8
        for (int d = 0; d < 64; d++) s += Qs[qq*65 + d] * Rk[r*64 + d];
        Sq[qq*33 + r] = s * 0.125f;
    }
    __syncthreads();

    float m0 = -1e30f, m1 = -1e30f, l0 = 0.f, l1 = 0.f;
    float oa0[8], oa1[8];
    #pragma unroll
    for (int i = 0; i < 8; i++) { oa0[i] = 0.f; oa1[i] = 0.f; }
    float e00 = 0.f, e032 = 0.f, e10 = 0.f, e132 = 0.f;

    for (int kt = 0; kt < 16; kt++) {
        __syncthreads();   // protect Ks/Vs/Ps from previous iteration
        const int kbase = kt << 6;
        for (int idx = tid; idx < 1024; idx += 256) {
            int r = idx >> 4, c = (idx & 15) << 2;
            size_t go = (size_t)(b*LSEQ + kbase + r) * DMODEL + h*64 + c;
            float4 kv = *(const float4*)(Km + go);
            float4 vv = *(const float4*)(Vm + go);
            Ks[r*65+c] = kv.x; Ks[r*65+c+1] = kv.y; Ks[r*65+c+2] = kv.z; Ks[r*65+c+3] = kv.w;
            Vs[r*65+c] = vv.x; Vs[r*65+c+1] = vv.y; Vs[r*65+c+2] = vv.z; Vs[r*65+c+3] = vv.w;
        }
        __syncthreads();

        float s0[8], s1[8];
        #pragma unroll
        for (int j = 0; j < 8; j++) { s0[j] = 0.f; s1[j] = 0.f; }
        for (int d = 0; d < 64; d++) {
            float qv0 = Qs[qa*65 + d], qv1 = Qs[qb*65 + d];
            #pragma unroll
            for (int j = 0; j < 8; j++) {
                float kvv = Ks[(sub + 8*j)*65 + d];
                s0[j] += qv0 * kvv;
                s1[j] += qv1 * kvv;
            }
        }
        float tm0 = -1e30f, tm1 = -1e30f;
        #pragma unroll
        for (int j = 0; j < 8; j++) {
            int kg = kbase + sub + 8*j;
            int d0 = kg - (q0 + qa);
            int r0 = d0 < -16 ? 0 : (d0 > 16 ? 32 : d0 + 16);
            s0[j] = s0[j] * 0.125f + Sq[qa*33 + r0];
            int d1 = kg - (q0 + qb);
            int r1 = d1 < -16 ? 0 : (d1 > 16 ? 32 : d1 + 16);
            s1[j] = s1[j] * 0.125f + Sq[qb*33 + r1];
            tm0 = fmaxf(tm0, s0[j]); tm1 = fmaxf(tm1, s1[j]);
        }
        #pragma unroll
        for (int o = 1; o < 8; o <<= 1) {
            tm0 = fmaxf(tm0, __shfl_xor_sync(0xffffffffu, tm0, o));
            tm1 = fmaxf(tm1, __shfl_xor_sync(0xffffffffu, tm1, o));
        }
        float mn0 = fmaxf(m0, tm0), mn1 = fmaxf(m1, tm1);
        float c0 = __expf(m0 - mn0), c1 = __expf(m1 - mn1);
        m0 = mn0; m1 = mn1;

        for (int r = sub; r <= 32; r += 8) {
            Tac[qa*33 + r] *= c0;
            Tac[qb*33 + r] *= c1;
        }
        e00 *= c0; e032 *= c0; e10 *= c1; e132 *= c1;
        #pragma unroll
        for (int i = 0; i < 8; i++) { oa0[i] *= c0; oa1[i] *= c1; }
        __syncwarp();

        float ts0 = 0.f, ts1 = 0.f;
        #pragma unroll
        for (int j = 0; j < 8; j++) {
            float p0 = __expf(s0[j] - m0);
            float p1 = __expf(s1[j] - m1);
            Ps[qa*65 + sub + 8*j] = p0;
            Ps[qb*65 + sub + 8*j] = p1;
            ts0 += p0; ts1 += p1;
            int kg = kbase + sub + 8*j;
            int d0 = kg - (q0 + qa);
            if (d0 <= -16)      e00 += p0;
            else if (d0 >= 16)  e032 += p0;
            else                Tac[qa*33 + d0 + 16] += p0;
            int d1 = kg - (q0 + qb);
            if (d1 <= -16)      e10 += p1;
            else if (d1 >= 16)  e132 += p1;
            else                Tac[qb*33 + d1 + 16] += p1;
        }
        #pragma unroll
        for (int o = 1; o < 8; o <<= 1) {
            ts0 += __shfl_xor_sync(0xffffffffu, ts0, o);
            ts1 += __shfl_xor_sync(0xffffffffu, ts1, o);
        }
        l0 = l0 * c0 + ts0;
        l1 = l1 * c1 + ts1;
        __syncwarp();

        for (int kj = 0; kj < 64; kj++) {
            float p0 = Ps[qa*65 + kj];
            float p1 = Ps[qb*65 + kj];
            #pragma unroll
            for (int i = 0; i < 8; i++) {
                float vv = Vs[kj*65 + sub + 8*i];
                oa0[i] += p0 * vv;
                oa1[i] += p1 * vv;
            }
        }
    }

    // fold edge buckets into Tac
    #pragma unroll
    for (int o = 1; o < 8; o <<= 1) {
        e00  += __shfl_xor_sync(0xffffffffu, e00, o);
        e032 += __shfl_xor_sync(0xffffffffu, e032, o);
        e10  += __shfl_xor_sync(0xffffffffu, e10, o);
        e132 += __shfl_xor_sync(0xffffffffu, e132, o);
    }
    if (sub == 0) {
        Tac[qa*33 + 0]  = e00;
        Tac[qa*33 + 32] = e032;
        Tac[qb*33 + 0]  = e10;
        Tac[qb*33 + 32] = e132;
    }
    __syncthreads();
    for (int idx = tid; idx < 528; idx += 256)
        ((float4*)Rv)[idx] = ((const float4*)relv)[idx];
    __syncthreads();

    // weight2 = T @ rel_v, add, normalize
    for (int r = 0; r < 33; r++) {
        float t0 = Tac[qa*33 + r], t1 = Tac[qb*33 + r];
        #pragma unroll
        for (int i = 0; i < 8; i++) {
            float rv = Rv[r*64 + sub + 8*i];
            oa0[i] += t0 * rv;
            oa1[i] += t1 * rv;
        }
    }
    float inv0 = 1.f / l0, inv1 = 1.f / l1;
    #pragma unroll
    for (int i = 0; i < 8; i++) {
        Ps[qa*65 + sub + 8*i] = oa0[i] * inv0;
        Ps[qb*65 + sub + 8*i] = oa1[i] * inv1;
    }
    __syncthreads();
    for (int idx = tid; idx < 1024; idx += 256) {
        int r = idx >> 4, c = (idx & 15) << 2;
        float4 o;
        o.x = Ps[r*65+c];   o.y = Ps[r*65+c+1];
        o.z = Ps[r*65+c+2]; o.w = Ps[r*65+c+3];
        *(float4*)(O + (size_t)(b*LSEQ + q0 + r) * DMODEL + h*64 + c) = o;
    }
}

// ---------------------------------------------------------------------------
// LayerNorm over rows of 1024
// ---------------------------------------------------------------------------
__global__ void ln_kernel(const float* __restrict__ X, const float* __restrict__ g,
                          const float* __restrict__ bta, float* __restrict__ Y)
{
    __shared__ float rs[18];
    const int row = blockIdx.x, tid = threadIdx.x;
    float4 v = ((const float4*)(X + (size_t)row * 1024))[tid];
    float s  = v.x + v.y + v.z + v.w;
    float s2 = v.x*v.x + v.y*v.y + v.z*v.z + v.w*v.w;
    #pragma unroll
    for (int o = 16; o > 0; o >>= 1) {
        s  += __shfl_down_sync(0xffffffffu, s, o);
        s2 += __shfl_down_sync(0xffffffffu, s2, o);
    }
    int wid = tid >> 5;
    if ((tid & 31) == 0) { rs[wid] = s; rs[8 + wid] = s2; }
    __syncthreads();
    if (tid == 0) {
        float ts = 0.f, ts2 = 0.f;
        for (int w = 0; w < 8; w++) { ts += rs[w]; ts2 += rs[8 + w]; }
        float mu = ts * (1.f / 1024.f);
        float var = ts2 * (1.f / 1024.f) - mu * mu;
        rs[16] = mu;
        rs[17] = rsqrtf(var + 1e-6f);
    }
    __syncthreads();
    float mu = rs[16], rstd = rs[17];
    float4 gg = ((const float4*)g)[tid];
    float4 bb = ((const float4*)bta)[tid];
    float4 o;
    o.x = (v.x - mu) * rstd * gg.x + bb.x;
    o.y = (v.y - mu) * rstd * gg.y + bb.y;
    o.z = (v.z - mu) * rstd * gg.z + bb.z;
    o.w = (v.w - mu) * rstd * gg.w + bb.w;
    ((float4*)(Y + (size_t)row * 1024))[tid] = o;
}

// ---------------------------------------------------------------------------
extern "C" void kernel_launch(void* const* d_in, const int* in_sizes, int n_in,
                              void* d_out, int out_size)
{
    const float* q    = (const float*)d_in[0];
    const float* k    = (const float*)d_in[1];
    const float* v    = (const float*)d_in[2];
    const float* wq   = (const float*)d_in[3];
    const float* bq   = (const float*)d_in[4];
    const float* wk   = (const float*)d_in[5];
    const float* bk   = (const float*)d_in[6];
    const float* wv   = (const float*)d_in[7];
    const float* bv   = (const float*)d_in[8];
    const float* wfc  = (const float*)d_in[9];
    const float* bfc  = (const float*)d_in[10];
    const float* w1   = (const float*)d_in[11];
    const float* b1   = (const float*)d_in[12];
    const float* w2   = (const float*)d_in[13];
    const float* b2   = (const float*)d_in[14];
    const float* lng  = (const float*)d_in[15];
    const float* lnb  = (const float*)d_in[16];
    const float* relk = (const float*)d_in[17];
    const float* relv = (const float*)d_in[18];
    float* out = (float*)d_out;

    float *Qp, *Kp, *Vp, *AOp, *T0p, *X1p, *Hp;
    cudaGetSymbolAddress((void**)&Qp,  g_Q);
    cudaGetSymbolAddress((void**)&Kp,  g_K);
    cudaGetSymbolAddress((void**)&Vp,  g_V);
    cudaGetSymbolAddress((void**)&AOp, g_AO);
    cudaGetSymbolAddress((void**)&T0p, g_T0);
    cudaGetSymbolAddress((void**)&X1p, g_X1);
    cudaGetSymbolAddress((void**)&Hp,  g_H);

    cudaFuncSetAttribute(attn_kernel, cudaFuncAttributeMaxDynamicSharedMemorySize, ATTN_SMEM);

    dim3 blk(256);
    dim3 g1024(1024 / 128, 8192 / 128);   // (8, 64)
    dim3 g4096(4096 / 128, 8192 / 128);   // (32, 64)

    gemm_kernel<<<g1024, blk>>>(q, wq, bq, nullptr, Qp, 1024, 1024, 0);
    gemm_kernel<<<g1024, blk>>>(k, wk, bk, nullptr, Kp, 1024, 1024, 0);
    gemm_kernel<<<g1024, blk>>>(v, wv, bv, nullptr, Vp, 1024, 1024, 0);

    attn_kernel<<<dim3(16, NHEAD, 8), blk, ATTN_SMEM>>>(Qp, Kp, Vp, relk, relv, AOp);

    gemm_kernel<<<g1024, blk>>>(AOp, wfc, bfc, q, T0p, 1024, 1024, 0);
    ln_kernel<<<8192, 256>>>(T0p, lng, lnb, X1p);

    gemm_kernel<<<g4096, blk>>>(X1p, w1, b1, nullptr, Hp, 4096, 1024, 1);
    gemm_kernel<<<g1024, blk>>>(Hp, w2, b2, X1p, T0p, 1024, 4096, 0);
    ln_kernel<<<8192, 256>>>(T0p, lng, lnb, out);
}

// round 6
// speedup vs baseline: 1.7756x; 1.7756x over previous
#include <cuda_runtime.h>
#include <math.h>
#include <stdint.h>

#define M_ROWS 8192
#define DMODEL 1024
#define DINNER 4096
#define LSEQ   1024
#define NHEAD  16

__device__ float g_Q [M_ROWS*DMODEL];
__device__ float g_K [M_ROWS*DMODEL];
__device__ float g_V [M_ROWS*DMODEL];
__device__ float g_AO[M_ROWS*DMODEL];
__device__ float g_T0[M_ROWS*DMODEL];
__device__ float g_X1[M_ROWS*DMODEL];
__device__ float g_H [M_ROWS*DINNER];

__device__ __forceinline__ float tf32r(float x) {
    uint32_t u;
    asm("cvt.rna.tf32.f32 %0, %1;" : "=r"(u) : "f"(x));
    return __uint_as_float(u);
}

// ---------------------------------------------------------------------------
// TF32 tensor-core GEMM: C[M,N] = A[M,K] @ W[K,N] + bias (+res) (relu?)
// 128x128 block tile, K-tile 16, 256 threads (8 warps, 4x2), warp = 32x64.
// A frags via conflict-free scalar LDS from [128][20] smem; B frags via
// conflict-free scalar LDS from [16][132] smem.
// ---------------------------------------------------------------------------
#define A_STRIDE 20
#define B_STRIDE 132

__global__ __launch_bounds__(256)
void gemm_tf32(const float* __restrict__ A, const float* __restrict__ W,
               const float* __restrict__ bias, const float* __restrict__ res,
               float* __restrict__ C, int N, int K, int relu)
{
    __shared__ __align__(16) float As[2][128 * A_STRIDE];
    __shared__ __align__(16) float Bs[2][16 * B_STRIDE];

    const int tid  = threadIdx.x;
    const int lane = tid & 31;
    const int warp = tid >> 5;
    const int wm = warp & 3, wn = warp >> 2;
    const int m0 = wm * 32, n0 = wn * 64;
    const int bm = blockIdx.y * 128, bn = blockIdx.x * 128;

    // global load mapping
    const int arow = tid >> 2, ac = (tid & 3) << 2;   // A: rows arow, arow+64
    const int brow = tid >> 5, bc = (tid & 31) << 2;  // B: rows brow, brow+8
    const float* ApA = A + (size_t)(bm + arow) * K + ac;
    const float* ApB = ApA + (size_t)64 * K;
    const float* WpA = W + (size_t)brow * N + bn + bc;
    const float* WpB = W + (size_t)(brow + 8) * N + bn + bc;

    float4 sa0 = *(const float4*)ApA;
    float4 sa1 = *(const float4*)ApB;
    float4 sb0 = *(const float4*)WpA;
    float4 sb1 = *(const float4*)WpB;

    {
        float* as = As[0];
        float* bs = Bs[0];
        float4 t;
        t.x = tf32r(sa0.x); t.y = tf32r(sa0.y); t.z = tf32r(sa0.z); t.w = tf32r(sa0.w);
        *(float4*)(as + arow * A_STRIDE + ac) = t;
        t.x = tf32r(sa1.x); t.y = tf32r(sa1.y); t.z = tf32r(sa1.z); t.w = tf32r(sa1.w);
        *(float4*)(as + (arow + 64) * A_STRIDE + ac) = t;
        t.x = tf32r(sb0.x); t.y = tf32r(sb0.y); t.z = tf32r(sb0.z); t.w = tf32r(sb0.w);
        *(float4*)(bs + brow * B_STRIDE + bc) = t;
        t.x = tf32r(sb1.x); t.y = tf32r(sb1.y); t.z = tf32r(sb1.z); t.w = tf32r(sb1.w);
        *(float4*)(bs + (brow + 8) * B_STRIDE + bc) = t;
    }
    __syncthreads();

    float acc[2][8][4];
    #pragma unroll
    for (int mt = 0; mt < 2; mt++)
        #pragma unroll
        for (int j = 0; j < 8; j++)
            #pragma unroll
            for (int e = 0; e < 4; e++) acc[mt][j][e] = 0.f;

    const int NT = K >> 4;
    for (int kt = 0; kt < NT; kt++) {
        const int cur = kt & 1;
        if (kt + 1 < NT) {
            const int k0g = (kt + 1) << 4;
            sa0 = *(const float4*)(ApA + k0g);
            sa1 = *(const float4*)(ApB + k0g);
            sb0 = *(const float4*)(WpA + (size_t)k0g * N);
            sb1 = *(const float4*)(WpB + (size_t)k0g * N);
        }

        const float* as = As[cur];
        const float* bs = Bs[cur];
        // per-lane base for A fragment scalar loads (conflict-free, see header)
        const float* ap = as + (size_t)(m0 + (lane >> 2)) * A_STRIDE + (lane & 3);

        #pragma unroll
        for (int ks = 0; ks < 2; ks++) {
            const int k0 = ks << 3;
            uint32_t afr[2][4];
            #pragma unroll
            for (int mt = 0; mt < 2; mt++) {
                afr[mt][0] = __float_as_uint(ap[(mt * 16    ) * A_STRIDE + k0    ]);
                afr[mt][1] = __float_as_uint(ap[(mt * 16 + 8) * A_STRIDE + k0    ]);
                afr[mt][2] = __float_as_uint(ap[(mt * 16    ) * A_STRIDE + k0 + 4]);
                afr[mt][3] = __float_as_uint(ap[(mt * 16 + 8) * A_STRIDE + k0 + 4]);
            }
            const float* bp = bs + (k0 + (lane & 3)) * B_STRIDE + n0 + (lane >> 2);
            #pragma unroll
            for (int j = 0; j < 8; j++) {
                uint32_t b0 = __float_as_uint(bp[j * 8]);
                uint32_t b1 = __float_as_uint(bp[j * 8 + 4 * B_STRIDE]);
                #pragma unroll
                for (int mt = 0; mt < 2; mt++) {
                    asm volatile(
                        "mma.sync.aligned.m16n8k8.row.col.f32.tf32.tf32.f32 "
                        "{%0,%1,%2,%3}, {%4,%5,%6,%7}, {%8,%9}, {%0,%1,%2,%3};"
                        : "+f"(acc[mt][j][0]), "+f"(acc[mt][j][1]),
                          "+f"(acc[mt][j][2]), "+f"(acc[mt][j][3])
                        : "r"(afr[mt][0]), "r"(afr[mt][1]),
                          "r"(afr[mt][2]), "r"(afr[mt][3]),
                          "r"(b0), "r"(b1));
                }
            }
        }

        if (kt + 1 < NT) {
            float* as2 = As[cur ^ 1];
            float* bs2 = Bs[cur ^ 1];
            float4 t;
            t.x = tf32r(sa0.x); t.y = tf32r(sa0.y); t.z = tf32r(sa0.z); t.w = tf32r(sa0.w);
            *(float4*)(as2 + arow * A_STRIDE + ac) = t;
            t.x = tf32r(sa1.x); t.y = tf32r(sa1.y); t.z = tf32r(sa1.z); t.w = tf32r(sa1.w);
            *(float4*)(as2 + (arow + 64) * A_STRIDE + ac) = t;
            t.x = tf32r(sb0.x); t.y = tf32r(sb0.y); t.z = tf32r(sb0.z); t.w = tf32r(sb0.w);
            *(float4*)(bs2 + brow * B_STRIDE + bc) = t;
            t.x = tf32r(sb1.x); t.y = tf32r(sb1.y); t.z = tf32r(sb1.z); t.w = tf32r(sb1.w);
            *(float4*)(bs2 + (brow + 8) * B_STRIDE + bc) = t;
        }
        __syncthreads();
    }

    // epilogue: C fragment c0,c1 -> (row, col..col+1); c2,c3 -> (row+8, ...)
    const int r_lane = lane >> 2;
    const int c_lane = (lane & 3) << 1;
    #pragma unroll
    for (int mt = 0; mt < 2; mt++) {
        const int row0 = bm + m0 + mt * 16 + r_lane;
        #pragma unroll
        for (int j = 0; j < 8; j++) {
            const int col = bn + n0 + j * 8 + c_lane;
            float2 bb = *(const float2*)(bias + col);
            float2 v0, v1;
            v0.x = acc[mt][j][0] + bb.x; v0.y = acc[mt][j][1] + bb.y;
            v1.x = acc[mt][j][2] + bb.x; v1.y = acc[mt][j][3] + bb.y;
            if (res) {
                float2 r0 = *(const float2*)(res + (size_t)row0 * N + col);
                float2 r1 = *(const float2*)(res + (size_t)(row0 + 8) * N + col);
                v0.x += r0.x; v0.y += r0.y;
                v1.x += r1.x; v1.y += r1.y;
            }
            if (relu) {
                v0.x = fmaxf(v0.x, 0.f); v0.y = fmaxf(v0.y, 0.f);
                v1.x = fmaxf(v1.x, 0.f); v1.y = fmaxf(v1.y, 0.f);
            }
            *(float2*)(C + (size_t)row0 * N + col) = v0;
            *(float2*)(C + (size_t)(row0 + 8) * N + col) = v1;
        }
    }
}

// ---------------------------------------------------------------------------
// Fused relative attention (unchanged)
// ---------------------------------------------------------------------------
#define ATTN_SMEM (20864 * 4)

__global__ __launch_bounds__(256, 2)
void attn_kernel(const float* __restrict__ Q, const float* __restrict__ Km,
                 const float* __restrict__ Vm, const float* __restrict__ relk,
                 const float* __restrict__ relv, float* __restrict__ O)
{
    extern __shared__ float smx[];
    float* Qs  = smx;             // [64][65]
    float* Ks  = smx + 4160;      // [64][65]
    float* Vs  = smx + 8320;      // [64][65]
    float* Ps  = smx + 12480;     // [64][65]
    float* Sq  = smx + 16640;     // [64][33]
    float* Tac = smx + 18752;     // [64][33]
    float* Rk  = Ps;
    float* Rv  = Ks;

    const int tid = threadIdx.x;
    const int b = blockIdx.z, h = blockIdx.y, qt = blockIdx.x;
    const int q0 = qt << 6;
    const int rp  = tid >> 3;
    const int sub = tid & 7;
    const int qa = rp * 2, qb = qa + 1;

    for (int idx = tid; idx < 1024; idx += 256) {
        int r = idx >> 4, c = (idx & 15) << 2;
        float4 qv = *(const float4*)(Q + (size_t)(b*LSEQ + q0 + r) * DMODEL + h*64 + c);
        Qs[r*65+c] = qv.x; Qs[r*65+c+1] = qv.y; Qs[r*65+c+2] = qv.z; Qs[r*65+c+3] = qv.w;
    }
    for (int idx = tid; idx < 528; idx += 256)
        ((float4*)Rk)[idx] = ((const float4*)relk)[idx];
    for (int idx = tid; idx < 2112; idx += 256) Tac[idx] = 0.f;
    __syncthreads();

    for (int idx = tid; idx < 2112; idx += 256) {
        int qq = idx / 33, r = idx - qq * 33;
        float s = 0.f;
        #pragma unroll 8
        for (int d = 0; d < 64; d++) s += Qs[qq*65 + d] * Rk[r*64 + d];
        Sq[qq*33 + r] = s * 0.125f;
    }
    __syncthreads();

    float m0 = -1e30f, m1 = -1e30f, l0 = 0.f, l1 = 0.f;
    float oa0[8], oa1[8];
    #pragma unroll
    for (int i = 0; i < 8; i++) { oa0[i] = 0.f; oa1[i] = 0.f; }
    float e00 = 0.f, e032 = 0.f, e10 = 0.f, e132 = 0.f;

    for (int kt = 0; kt < 16; kt++) {
        __syncthreads();
        const int kbase = kt << 6;
        for (int idx = tid; idx < 1024; idx += 256) {
            int r = idx >> 4, c = (idx & 15) << 2;
            size_t go = (size_t)(b*LSEQ + kbase + r) * DMODEL + h*64 + c;
            float4 kv = *(const float4*)(Km + go);
            float4 vv = *(const float4*)(Vm + go);
            Ks[r*65+c] = kv.x; Ks[r*65+c+1] = kv.y; Ks[r*65+c+2] = kv.z; Ks[r*65+c+3] = kv.w;
            Vs[r*65+c] = vv.x; Vs[r*65+c+1] = vv.y; Vs[r*65+c+2] = vv.z; Vs[r*65+c+3] = vv.w;
        }
        __syncthreads();

        float s0[8], s1[8];
        #pragma unroll
        for (int j = 0; j < 8; j++) { s0[j] = 0.f; s1[j] = 0.f; }
        for (int d = 0; d < 64; d++) {
            float qv0 = Qs[qa*65 + d], qv1 = Qs[qb*65 + d];
            #pragma unroll
            for (int j = 0; j < 8; j++) {
                float kvv = Ks[(sub + 8*j)*65 + d];
                s0[j] += qv0 * kvv;
                s1[j] += qv1 * kvv;
            }
        }
        float tm0 = -1e30f, tm1 = -1e30f;
        #pragma unroll
        for (int j = 0; j < 8; j++) {
            int kg = kbase + sub + 8*j;
            int d0 = kg - (q0 + qa);
            int r0 = d0 < -16 ? 0 : (d0 > 16 ? 32 : d0 + 16);
            s0[j] = s0[j] * 0.125f + Sq[qa*33 + r0];
            int d1 = kg - (q0 + qb);
            int r1 = d1 < -16 ? 0 : (d1 > 16 ? 32 : d1 + 16);
            s1[j] = s1[j] * 0.125f + Sq[qb*33 + r1];
            tm0 = fmaxf(tm0, s0[j]); tm1 = fmaxf(tm1, s1[j]);
        }
        #pragma unroll
        for (int o = 1; o < 8; o <<= 1) {
            tm0 = fmaxf(tm0, __shfl_xor_sync(0xffffffffu, tm0, o));
            tm1 = fmaxf(tm1, __shfl_xor_sync(0xffffffffu, tm1, o));
        }
        float mn0 = fmaxf(m0, tm0), mn1 = fmaxf(m1, tm1);
        float c0 = __expf(m0 - mn0), c1 = __expf(m1 - mn1);
        m0 = mn0; m1 = mn1;

        for (int r = sub; r <= 32; r += 8) {
            Tac[qa*33 + r] *= c0;
            Tac[qb*33 + r] *= c1;
        }
        e00 *= c0; e032 *= c0; e10 *= c1; e132 *= c1;
        #pragma unroll
        for (int i = 0; i < 8; i++) { oa0[i] *= c0; oa1[i] *= c1; }
        __syncwarp();

        float ts0 = 0.f, ts1 = 0.f;
        #pragma unroll
        for (int j = 0; j < 8; j++) {
            float p0 = __expf(s0[j] - m0);
            float p1 = __expf(s1[j] - m1);
            Ps[qa*65 + sub + 8*j] = p0;
            Ps[qb*65 + sub + 8*j] = p1;
            ts0 += p0; ts1 += p1;
            int kg = kbase + sub + 8*j;
            int d0 = kg - (q0 + qa);
            if (d0 <= -16)      e00 += p0;
            else if (d0 >= 16)  e032 += p0;
            else                Tac[qa*33 + d0 + 16] += p0;
            int d1 = kg - (q0 + qb);
            if (d1 <= -16)      e10 += p1;
            else if (d1 >= 16)  e132 += p1;
            else                Tac[qb*33 + d1 + 16] += p1;
        }
        #pragma unroll
        for (int o = 1; o < 8; o <<= 1) {
            ts0 += __shfl_xor_sync(0xffffffffu, ts0, o);
            ts1 += __shfl_xor_sync(0xffffffffu, ts1, o);
        }
        l0 = l0 * c0 + ts0;
        l1 = l1 * c1 + ts1;
        __syncwarp();

        for (int kj = 0; kj < 64; kj++) {
            float p0 = Ps[qa*65 + kj];
            float p1 = Ps[qb*65 + kj];
            #pragma unroll
            for (int i = 0; i < 8; i++) {
                float vv = Vs[kj*65 + sub + 8*i];
                oa0[i] += p0 * vv;
                oa1[i] += p1 * vv;
            }
        }
    }

    #pragma unroll
    for (int o = 1; o < 8; o <<= 1) {
        e00  += __shfl_xor_sync(0xffffffffu, e00, o);
        e032 += __shfl_xor_sync(0xffffffffu, e032, o);
        e10  += __shfl_xor_sync(0xffffffffu, e10, o);
        e132 += __shfl_xor_sync(0xffffffffu, e132, o);
    }
    if (sub == 0) {
        Tac[qa*33 + 0]  = e00;
        Tac[qa*33 + 32] = e032;
        Tac[qb*33 + 0]  = e10;
        Tac[qb*33 + 32] = e132;
    }
    __syncthreads();
    for (int idx = tid; idx < 528; idx += 256)
        ((float4*)Rv)[idx] = ((const float4*)relv)[idx];
    __syncthreads();

    for (int r = 0; r < 33; r++) {
        float t0 = Tac[qa*33 + r], t1 = Tac[qb*33 + r];
        #pragma unroll
        for (int i = 0; i < 8; i++) {
            float rv = Rv[r*64 + sub + 8*i];
            oa0[i] += t0 * rv;
            oa1[i] += t1 * rv;
        }
    }
    float inv0 = 1.f / l0, inv1 = 1.f / l1;
    #pragma unroll
    for (int i = 0; i < 8; i++) {
        Ps[qa*65 + sub + 8*i] = oa0[i] * inv0;
        Ps[qb*65 + sub + 8*i] = oa1[i] * inv1;
    }
    __syncthreads();
    for (int idx = tid; idx < 1024; idx += 256) {
        int r = idx >> 4, c = (idx & 15) << 2;
        float4 o;
        o.x = Ps[r*65+c];   o.y = Ps[r*65+c+1];
        o.z = Ps[r*65+c+2]; o.w = Ps[r*65+c+3];
        *(float4*)(O + (size_t)(b*LSEQ + q0 + r) * DMODEL + h*64 + c) = o;
    }
}

// ---------------------------------------------------------------------------
// LayerNorm over rows of 1024
// ---------------------------------------------------------------------------
__global__ void ln_kernel(const float* __restrict__ X, const float* __restrict__ g,
                          const float* __restrict__ bta, float* __restrict__ Y)
{
    __shared__ float rs[18];
    const int row = blockIdx.x, tid = threadIdx.x;
    float4 v = ((const float4*)(X + (size_t)row * 1024))[tid];
    float s  = v.x + v.y + v.z + v.w;
    float s2 = v.x*v.x + v.y*v.y + v.z*v.z + v.w*v.w;
    #pragma unroll
    for (int o = 16; o > 0; o >>= 1) {
        s  += __shfl_down_sync(0xffffffffu, s, o);
        s2 += __shfl_down_sync(0xffffffffu, s2, o);
    }
    int wid = tid >> 5;
    if ((tid & 31) == 0) { rs[wid] = s; rs[8 + wid] = s2; }
    __syncthreads();
    if (tid == 0) {
        float ts = 0.f, ts2 = 0.f;
        for (int w = 0; w < 8; w++) { ts += rs[w]; ts2 += rs[8 + w]; }
        float mu = ts * (1.f / 1024.f);
        float var = ts2 * (1.f / 1024.f) - mu * mu;
        rs[16] = mu;
        rs[17] = rsqrtf(var + 1e-6f);
    }
    __syncthreads();
    float mu = rs[16], rstd = rs[17];
    float4 gg = ((const float4*)g)[tid];
    float4 bb = ((const float4*)bta)[tid];
    float4 o;
    o.x = (v.x - mu) * rstd * gg.x + bb.x;
    o.y = (v.y - mu) * rstd * gg.y + bb.y;
    o.z = (v.z - mu) * rstd * gg.z + bb.z;
    o.w = (v.w - mu) * rstd * gg.w + bb.w;
    ((float4*)(Y + (size_t)row * 1024))[tid] = o;
}

// ---------------------------------------------------------------------------
extern "C" void kernel_launch(void* const* d_in, const int* in_sizes, int n_in,
                              void* d_out, int out_size)
{
    const float* q    = (const float*)d_in[0];
    const float* k    = (const float*)d_in[1];
    const float* v    = (const float*)d_in[2];
    const float* wq   = (const float*)d_in[3];
    const float* bq   = (const float*)d_in[4];
    const float* wk   = (const float*)d_in[5];
    const float* bk   = (const float*)d_in[6];
    const float* wv   = (const float*)d_in[7];
    const float* bv   = (const float*)d_in[8];
    const float* wfc  = (const float*)d_in[9];
    const float* bfc  = (const float*)d_in[10];
    const float* w1   = (const float*)d_in[11];
    const float* b1   = (const float*)d_in[12];
    const float* w2   = (const float*)d_in[13];
    const float* b2   = (const float*)d_in[14];
    const float* lng  = (const float*)d_in[15];
    const float* lnb  = (const float*)d_in[16];
    const float* relk = (const float*)d_in[17];
    const float* relv = (const float*)d_in[18];
    float* out = (float*)d_out;

    float *Qp, *Kp, *Vp, *AOp, *T0p, *X1p, *Hp;
    cudaGetSymbolAddress((void**)&Qp,  g_Q);
    cudaGetSymbolAddress((void**)&Kp,  g_K);
    cudaGetSymbolAddress((void**)&Vp,  g_V);
    cudaGetSymbolAddress((void**)&AOp, g_AO);
    cudaGetSymbolAddress((void**)&T0p, g_T0);
    cudaGetSymbolAddress((void**)&X1p, g_X1);
    cudaGetSymbolAddress((void**)&Hp,  g_H);

    cudaFuncSetAttribute(attn_kernel, cudaFuncAttributeMaxDynamicSharedMemorySize, ATTN_SMEM);

    dim3 blk(256);
    dim3 g1024(1024 / 128, 8192 / 128);   // (8, 64)
    dim3 g4096(4096 / 128, 8192 / 128);   // (32, 64)

    gemm_tf32<<<g1024, blk>>>(q, wq, bq, nullptr, Qp, 1024, 1024, 0);
    gemm_tf32<<<g1024, blk>>>(k, wk, bk, nullptr, Kp, 1024, 1024, 0);
    gemm_tf32<<<g1024, blk>>>(v, wv, bv, nullptr, Vp, 1024, 1024, 0);

    attn_kernel<<<dim3(16, NHEAD, 8), blk, ATTN_SMEM>>>(Qp, Kp, Vp, relk, relv, AOp);

    gemm_tf32<<<g1024, blk>>>(AOp, wfc, bfc, q, T0p, 1024, 1024, 0);
    ln_kernel<<<8192, 256>>>(T0p, lng, lnb, X1p);

    gemm_tf32<<<g4096, blk>>>(X1p, w1, b1, nullptr, Hp, 4096, 1024, 1);
    gemm_tf32<<<g1024, blk>>>(Hp, w2, b2, X1p, T0p, 1024, 4096, 0);
    ln_kernel<<<8192, 256>>>(T0p, lng, lnb, out);
}

// round 7
// speedup vs baseline: 1.9787x; 1.1144x over previous
#include <cuda_runtime.h>
#include <math.h>
#include <stdint.h>

#define M_ROWS 8192
#define DMODEL 1024
#define DINNER 4096
#define LSEQ   1024
#define NHEAD  16

__device__ float g_Q [M_ROWS*DMODEL];
__device__ float g_K [M_ROWS*DMODEL];
__device__ float g_V [M_ROWS*DMODEL];
__device__ float g_AO[M_ROWS*DMODEL];
__device__ float g_T0[M_ROWS*DMODEL];
__device__ float g_X1[M_ROWS*DMODEL];
__device__ float g_H [M_ROWS*DINNER];

__device__ __forceinline__ void cpa16(void* smem, const void* gmem) {
    uint32_t s = (uint32_t)__cvta_generic_to_shared(smem);
    asm volatile("cp.async.cg.shared.global [%0], [%1], 16;\n" :: "r"(s), "l"(gmem));
}
__device__ __forceinline__ void cpa_commit() {
    asm volatile("cp.async.commit_group;\n" ::);
}
template<int N>
__device__ __forceinline__ void cpa_wait() {
    asm volatile("cp.async.wait_group %0;\n" :: "n"(N));
}

// ---------------------------------------------------------------------------
// TF32 tensor-core GEMM: C[M,N] = A[M,K] @ W[K,N] + bias (+res) (relu?)
// 128x128 block tile, K-tile 16, 256 threads (8 warps, 4x2), warp = 32x64.
// 4-stage cp.async pipeline; raw fp32 in smem (tf32 MMA truncates mantissa).
// A frags + B frags via conflict-free scalar LDS.
// ---------------------------------------------------------------------------
#define A_STRIDE 20
#define B_STRIDE 132
#define STAGES 4

__global__ __launch_bounds__(256, 2)
void gemm_tf32(const float* __restrict__ A, const float* __restrict__ W,
               const float* __restrict__ bias, const float* __restrict__ res,
               float* __restrict__ C, int N, int K, int relu)
{
    __shared__ __align__(16) float As[STAGES][128 * A_STRIDE];
    __shared__ __align__(16) float Bs[STAGES][16 * B_STRIDE];

    const int tid  = threadIdx.x;
    const int lane = tid & 31;
    const int warp = tid >> 5;
    const int wm = warp & 3, wn = warp >> 2;
    const int m0 = wm * 32, n0 = wn * 64;
    const int bm = blockIdx.y * 128, bn = blockIdx.x * 128;

    // global load mapping
    const int arow = tid >> 2, ac = (tid & 3) << 2;   // A: rows arow, arow+64
    const int brow = tid >> 5, bc = (tid & 31) << 2;  // B: rows brow, brow+8
    const float* ApA = A + (size_t)(bm + arow) * K + ac;
    const float* ApB = ApA + (size_t)64 * K;
    const float* WpA = W + (size_t)brow * N + bn + bc;
    const float* WpB = W + (size_t)(brow + 8) * N + bn + bc;

    const int NT = K >> 4;

    // prologue: fill STAGES-1 stages
    #pragma unroll
    for (int s = 0; s < STAGES - 1; s++) {
        const int k0g = s << 4;
        cpa16(&As[s][arow * A_STRIDE + ac],        ApA + k0g);
        cpa16(&As[s][(arow + 64) * A_STRIDE + ac], ApB + k0g);
        cpa16(&Bs[s][brow * B_STRIDE + bc],        WpA + (size_t)k0g * N);
        cpa16(&Bs[s][(brow + 8) * B_STRIDE + bc],  WpB + (size_t)k0g * N);
        cpa_commit();
    }
    cpa_wait<STAGES - 2>();
    __syncthreads();

    float acc[2][8][4];
    #pragma unroll
    for (int mt = 0; mt < 2; mt++)
        #pragma unroll
        for (int j = 0; j < 8; j++)
            #pragma unroll
            for (int e = 0; e < 4; e++) acc[mt][j][e] = 0.f;

    for (int kt = 0; kt < NT; kt++) {
        const int cur = kt & (STAGES - 1);

        // issue loads for kt+STAGES-1 into the slot freed last iteration
        const int ktn = kt + STAGES - 1;
        if (ktn < NT) {
            const int sn = ktn & (STAGES - 1);
            const int k0g = ktn << 4;
            cpa16(&As[sn][arow * A_STRIDE + ac],        ApA + k0g);
            cpa16(&As[sn][(arow + 64) * A_STRIDE + ac], ApB + k0g);
            cpa16(&Bs[sn][brow * B_STRIDE + bc],        WpA + (size_t)k0g * N);
            cpa16(&Bs[sn][(brow + 8) * B_STRIDE + bc],  WpB + (size_t)k0g * N);
        }
        cpa_commit();

        const float* as = As[cur];
        const float* bs = Bs[cur];
        // per-lane base for A fragment scalar loads (conflict-free)
        const float* ap = as + (size_t)(m0 + (lane >> 2)) * A_STRIDE + (lane & 3);

        #pragma unroll
        for (int ks = 0; ks < 2; ks++) {
            const int k0 = ks << 3;
            uint32_t afr[2][4];
            #pragma unroll
            for (int mt = 0; mt < 2; mt++) {
                afr[mt][0] = __float_as_uint(ap[(mt * 16    ) * A_STRIDE + k0    ]);
                afr[mt][1] = __float_as_uint(ap[(mt * 16 + 8) * A_STRIDE + k0    ]);
                afr[mt][2] = __float_as_uint(ap[(mt * 16    ) * A_STRIDE + k0 + 4]);
                afr[mt][3] = __float_as_uint(ap[(mt * 16 + 8) * A_STRIDE + k0 + 4]);
            }
            const float* bp = bs + (k0 + (lane & 3)) * B_STRIDE + n0 + (lane >> 2);
            #pragma unroll
            for (int j = 0; j < 8; j++) {
                uint32_t b0 = __float_as_uint(bp[j * 8]);
                uint32_t b1 = __float_as_uint(bp[j * 8 + 4 * B_STRIDE]);
                #pragma unroll
                for (int mt = 0; mt < 2; mt++) {
                    asm volatile(
                        "mma.sync.aligned.m16n8k8.row.col.f32.tf32.tf32.f32 "
                        "{%0,%1,%2,%3}, {%4,%5,%6,%7}, {%8,%9}, {%0,%1,%2,%3};"
                        : "+f"(acc[mt][j][0]), "+f"(acc[mt][j][1]),
                          "+f"(acc[mt][j][2]), "+f"(acc[mt][j][3])
                        : "r"(afr[mt][0]), "r"(afr[mt][1]),
                          "r"(afr[mt][2]), "r"(afr[mt][3]),
                          "r"(b0), "r"(b1));
                }
            }
        }

        cpa_wait<STAGES - 2>();
        __syncthreads();
    }

    // epilogue: C fragment c0,c1 -> (row, col..col+1); c2,c3 -> (row+8, ...)
    const int r_lane = lane >> 2;
    const int c_lane = (lane & 3) << 1;
    #pragma unroll
    for (int mt = 0; mt < 2; mt++) {
        const int row0 = bm + m0 + mt * 16 + r_lane;
        #pragma unroll
        for (int j = 0; j < 8; j++) {
            const int col = bn + n0 + j * 8 + c_lane;
            float2 bb = *(const float2*)(bias + col);
            float2 v0, v1;
            v0.x = acc[mt][j][0] + bb.x; v0.y = acc[mt][j][1] + bb.y;
            v1.x = acc[mt][j][2] + bb.x; v1.y = acc[mt][j][3] + bb.y;
            if (res) {
                float2 r0 = *(const float2*)(res + (size_t)row0 * N + col);
                float2 r1 = *(const float2*)(res + (size_t)(row0 + 8) * N + col);
                v0.x += r0.x; v0.y += r0.y;
                v1.x += r1.x; v1.y += r1.y;
            }
            if (relu) {
                v0.x = fmaxf(v0.x, 0.f); v0.y = fmaxf(v0.y, 0.f);
                v1.x = fmaxf(v1.x, 0.f); v1.y = fmaxf(v1.y, 0.f);
            }
            *(float2*)(C + (size_t)row0 * N + col) = v0;
            *(float2*)(C + (size_t)(row0 + 8) * N + col) = v1;
        }
    }
}

// ---------------------------------------------------------------------------
// Fused relative attention (unchanged)
// ---------------------------------------------------------------------------
#define ATTN_SMEM (20864 * 4)

__global__ __launch_bounds__(256, 2)
void attn_kernel(const float* __restrict__ Q, const float* __restrict__ Km,
                 const float* __restrict__ Vm, const float* __restrict__ relk,
                 const float* __restrict__ relv, float* __restrict__ O)
{
    extern __shared__ float smx[];
    float* Qs  = smx;             // [64][65]
    float* Ks  = smx + 4160;      // [64][65]
    float* Vs  = smx + 8320;      // [64][65]
    float* Ps  = smx + 12480;     // [64][65]
    float* Sq  = smx + 16640;     // [64][33]
    float* Tac = smx + 18752;     // [64][33]
    float* Rk  = Ps;
    float* Rv  = Ks;

    const int tid = threadIdx.x;
    const int b = blockIdx.z, h = blockIdx.y, qt = blockIdx.x;
    const int q0 = qt << 6;
    const int rp  = tid >> 3;
    const int sub = tid & 7;
    const int qa = rp * 2, qb = qa + 1;

    for (int idx = tid; idx < 1024; idx += 256) {
        int r = idx >> 4, c = (idx & 15) << 2;
        float4 qv = *(const float4*)(Q + (size_t)(b*LSEQ + q0 + r) * DMODEL + h*64 + c);
        Qs[r*65+c] = qv.x; Qs[r*65+c+1] = qv.y; Qs[r*65+c+2] = qv.z; Qs[r*65+c+3] = qv.w;
    }
    for (int idx = tid; idx < 528; idx += 256)
        ((float4*)Rk)[idx] = ((const float4*)relk)[idx];
    for (int idx = tid; idx < 2112; idx += 256) Tac[idx] = 0.f;
    __syncthreads();

    for (int idx = tid; idx < 2112; idx += 256) {
        int qq = idx / 33, r = idx - qq * 33;
        float s = 0.f;
        #pragma unroll 8
        for (int d = 0; d < 64; d++) s += Qs[qq*65 + d] * Rk[r*64 + d];
        Sq[qq*33 + r] = s * 0.125f;
    }
    __syncthreads();

    float m0 = -1e30f, m1 = -1e30f, l0 = 0.f, l1 = 0.f;
    float oa0[8], oa1[8];
    #pragma unroll
    for (int i = 0; i < 8; i++) { oa0[i] = 0.f; oa1[i] = 0.f; }
    float e00 = 0.f, e032 = 0.f, e10 = 0.f, e132 = 0.f;

    for (int kt = 0; kt < 16; kt++) {
        __syncthreads();
        const int kbase = kt << 6;
        for (int idx = tid; idx < 1024; idx += 256) {
            int r = idx >> 4, c = (idx & 15) << 2;
            size_t go = (size_t)(b*LSEQ + kbase + r) * DMODEL + h*64 + c;
            float4 kv = *(const float4*)(Km + go);
            float4 vv = *(const float4*)(Vm + go);
            Ks[r*65+c] = kv.x; Ks[r*65+c+1] = kv.y; Ks[r*65+c+2] = kv.z; Ks[r*65+c+3] = kv.w;
            Vs[r*65+c] = vv.x; Vs[r*65+c+1] = vv.y; Vs[r*65+c+2] = vv.z; Vs[r*65+c+3] = vv.w;
        }
        __syncthreads();

        float s0[8], s1[8];
        #pragma unroll
        for (int j = 0; j < 8; j++) { s0[j] = 0.f; s1[j] = 0.f; }
        for (int d = 0; d < 64; d++) {
            float qv0 = Qs[qa*65 + d], qv1 = Qs[qb*65 + d];
            #pragma unroll
            for (int j = 0; j < 8; j++) {
                float kvv = Ks[(sub + 8*j)*65 + d];
                s0[j] += qv0 * kvv;
                s1[j] += qv1 * kvv;
            }
        }
        float tm0 = -1e30f, tm1 = -1e30f;
        #pragma unroll
        for (int j = 0; j < 8; j++) {
            int kg = kbase + sub + 8*j;
            int d0 = kg - (q0 + qa);
            int r0 = d0 < -16 ? 0 : (d0 > 16 ? 32 : d0 + 16);
            s0[j] = s0[j] * 0.125f + Sq[qa*33 + r0];
            int d1 = kg - (q0 + qb);
            int r1 = d1 < -16 ? 0 : (d1 > 16 ? 32 : d1 + 16);
            s1[j] = s1[j] * 0.125f + Sq[qb*33 + r1];
            tm0 = fmaxf(tm0, s0[j]); tm1 = fmaxf(tm1, s1[j]);
        }
        #pragma unroll
        for (int o = 1; o < 8; o <<= 1) {
            tm0 = fmaxf(tm0, __shfl_xor_sync(0xffffffffu, tm0, o));
            tm1 = fmaxf(tm1, __shfl_xor_sync(0xffffffffu, tm1, o));
        }
        float mn0 = fmaxf(m0, tm0), mn1 = fmaxf(m1, tm1);
        float c0 = __expf(m0 - mn0), c1 = __expf(m1 - mn1);
        m0 = mn0; m1 = mn1;

        for (int r = sub; r <= 32; r += 8) {
            Tac[qa*33 + r] *= c0;
            Tac[qb*33 + r] *= c1;
        }
        e00 *= c0; e032 *= c0; e10 *= c1; e132 *= c1;
        #pragma unroll
        for (int i = 0; i < 8; i++) { oa0[i] *= c0; oa1[i] *= c1; }
        __syncwarp();

        float ts0 = 0.f, ts1 = 0.f;
        #pragma unroll
        for (int j = 0; j < 8; j++) {
            float p0 = __expf(s0[j] - m0);
            float p1 = __expf(s1[j] - m1);
            Ps[qa*65 + sub + 8*j] = p0;
            Ps[qb*65 + sub + 8*j] = p1;
            ts0 += p0; ts1 += p1;
            int kg = kbase + sub + 8*j;
            int d0 = kg - (q0 + qa);
            if (d0 <= -16)      e00 += p0;
            else if (d0 >= 16)  e032 += p0;
            else                Tac[qa*33 + d0 + 16] += p0;
            int d1 = kg - (q0 + qb);
            if (d1 <= -16)      e10 += p1;
            else if (d1 >= 16)  e132 += p1;
            else                Tac[qb*33 + d1 + 16] += p1;
        }
        #pragma unroll
        for (int o = 1; o < 8; o <<= 1) {
            ts0 += __shfl_xor_sync(0xffffffffu, ts0, o);
            ts1 += __shfl_xor_sync(0xffffffffu, ts1, o);
        }
        l0 = l0 * c0 + ts0;
        l1 = l1 * c1 + ts1;
        __syncwarp();

        for (int kj = 0; kj < 64; kj++) {
            float p0 = Ps[qa*65 + kj];
            float p1 = Ps[qb*65 + kj];
            #pragma unroll
            for (int i = 0; i < 8; i++) {
                float vv = Vs[kj*65 + sub + 8*i];
                oa0[i] += p0 * vv;
                oa1[i] += p1 * vv;
            }
        }
    }

    #pragma unroll
    for (int o = 1; o < 8; o <<= 1) {
        e00  += __shfl_xor_sync(0xffffffffu, e00, o);
        e032 += __shfl_xor_sync(0xffffffffu, e032, o);
        e10  += __shfl_xor_sync(0xffffffffu, e10, o);
        e132 += __shfl_xor_sync(0xffffffffu, e132, o);
    }
    if (sub == 0) {
        Tac[qa*33 + 0]  = e00;
        Tac[qa*33 + 32] = e032;
        Tac[qb*33 + 0]  = e10;
        Tac[qb*33 + 32] = e132;
    }
    __syncthreads();
    for (int idx = tid; idx < 528; idx += 256)
        ((float4*)Rv)[idx] = ((const float4*)relv)[idx];
    __syncthreads();

    for (int r = 0; r < 33; r++) {
        float t0 = Tac[qa*33 + r], t1 = Tac[qb*33 + r];
        #pragma unroll
        for (int i = 0; i < 8; i++) {
            float rv = Rv[r*64 + sub + 8*i];
            oa0[i] += t0 * rv;
            oa1[i] += t1 * rv;
        }
    }
    float inv0 = 1.f / l0, inv1 = 1.f / l1;
    #pragma unroll
    for (int i = 0; i < 8; i++) {
        Ps[qa*65 + sub + 8*i] = oa0[i] * inv0;
        Ps[qb*65 + sub + 8*i] = oa1[i] * inv1;
    }
    __syncthreads();
    for (int idx = tid; idx < 1024; idx += 256) {
        int r = idx >> 4, c = (idx & 15) << 2;
        float4 o;
        o.x = Ps[r*65+c];   o.y = Ps[r*65+c+1];
        o.z = Ps[r*65+c+2]; o.w = Ps[r*65+c+3];
        *(float4*)(O + (size_t)(b*LSEQ + q0 + r) * DMODEL + h*64 + c) = o;
    }
}

// ---------------------------------------------------------------------------
// LayerNorm over rows of 1024
// ---------------------------------------------------------------------------
__global__ void ln_kernel(const float* __restrict__ X, const float* __restrict__ g,
                          const float* __restrict__ bta, float* __restrict__ Y)
{
    __shared__ float rs[18];
    const int row = blockIdx.x, tid = threadIdx.x;
    float4 v = ((const float4*)(X + (size_t)row * 1024))[tid];
    float s  = v.x + v.y + v.z + v.w;
    float s2 = v.x*v.x + v.y*v.y + v.z*v.z + v.w*v.w;
    #pragma unroll
    for (int o = 16; o > 0; o >>= 1) {
        s  += __shfl_down_sync(0xffffffffu, s, o);
        s2 += __shfl_down_sync(0xffffffffu, s2, o);
    }
    int wid = tid >> 5;
    if ((tid & 31) == 0) { rs[wid] = s; rs[8 + wid] = s2; }
    __syncthreads();
    if (tid == 0) {
        float ts = 0.f, ts2 = 0.f;
        for (int w = 0; w < 8; w++) { ts += rs[w]; ts2 += rs[8 + w]; }
        float mu = ts * (1.f / 1024.f);
        float var = ts2 * (1.f / 1024.f) - mu * mu;
        rs[16] = mu;
        rs[17] = rsqrtf(var + 1e-6f);
    }
    __syncthreads();
    float mu = rs[16], rstd = rs[17];
    float4 gg = ((const float4*)g)[tid];
    float4 bb = ((const float4*)bta)[tid];
    float4 o;
    o.x = (v.x - mu) * rstd * gg.x + bb.x;
    o.y = (v.y - mu) * rstd * gg.y + bb.y;
    o.z = (v.z - mu) * rstd * gg.z + bb.z;
    o.w = (v.w - mu) * rstd * gg.w + bb.w;
    ((float4*)(Y + (size_t)row * 1024))[tid] = o;
}

// ---------------------------------------------------------------------------
extern "C" void kernel_launch(void* const* d_in, const int* in_sizes, int n_in,
                              void* d_out, int out_size)
{
    const float* q    = (const float*)d_in[0];
    const float* k    = (const float*)d_in[1];
    const float* v    = (const float*)d_in[2];
    const float* wq   = (const float*)d_in[3];
    const float* bq   = (const float*)d_in[4];
    const float* wk   = (const float*)d_in[5];
    const float* bk   = (const float*)d_in[6];
    const float* wv   = (const float*)d_in[7];
    const float* bv   = (const float*)d_in[8];
    const float* wfc  = (const float*)d_in[9];
    const float* bfc  = (const float*)d_in[10];
    const float* w1   = (const float*)d_in[11];
    const float* b1   = (const float*)d_in[12];
    const float* w2   = (const float*)d_in[13];
    const float* b2   = (const float*)d_in[14];
    const float* lng  = (const float*)d_in[15];
    const float* lnb  = (const float*)d_in[16];
    const float* relk = (const float*)d_in[17];
    const float* relv = (const float*)d_in[18];
    float* out = (float*)d_out;

    float *Qp, *Kp, *Vp, *AOp, *T0p, *X1p, *Hp;
    cudaGetSymbolAddress((void**)&Qp,  g_Q);
    cudaGetSymbolAddress((void**)&Kp,  g_K);
    cudaGetSymbolAddress((void**)&Vp,  g_V);
    cudaGetSymbolAddress((void**)&AOp, g_AO);
    cudaGetSymbolAddress((void**)&T0p, g_T0);
    cudaGetSymbolAddress((void**)&X1p, g_X1);
    cudaGetSymbolAddress((void**)&Hp,  g_H);

    cudaFuncSetAttribute(attn_kernel, cudaFuncAttributeMaxDynamicSharedMemorySize, ATTN_SMEM);

    dim3 blk(256);
    dim3 g1024(1024 / 128, 8192 / 128);   // (8, 64)
    dim3 g4096(4096 / 128, 8192 / 128);   // (32, 64)

    gemm_tf32<<<g1024, blk>>>(q, wq, bq, nullptr, Qp, 1024, 1024, 0);
    gemm_tf32<<<g1024, blk>>>(k, wk, bk, nullptr, Kp, 1024, 1024, 0);
    gemm_tf32<<<g1024, blk>>>(v, wv, bv, nullptr, Vp, 1024, 1024, 0);

    attn_kernel<<<dim3(16, NHEAD, 8), blk, ATTN_SMEM>>>(Qp, Kp, Vp, relk, relv, AOp);

    gemm_tf32<<<g1024, blk>>>(AOp, wfc, bfc, q, T0p, 1024, 1024, 0);
    ln_kernel<<<8192, 256>>>(T0p, lng, lnb, X1p);

    gemm_tf32<<<g4096, blk>>>(X1p, w1, b1, nullptr, Hp, 4096, 1024, 1);
    gemm_tf32<<<g1024, blk>>>(Hp, w2, b2, X1p, T0p, 1024, 4096, 0);
    ln_kernel<<<8192, 256>>>(T0p, lng, lnb, out);
}

// round 11
// speedup vs baseline: 2.7633x; 1.3965x over previous
#include <cuda_runtime.h>
#include <math.h>
#include <stdint.h>

#define M_ROWS 8192
#define DMODEL 1024
#define DINNER 4096
#define LSEQ   1024
#define NHEAD  16

__device__ float g_Q  [M_ROWS*DMODEL];
__device__ float g_K  [M_ROWS*DMODEL];
__device__ float g_V  [M_ROWS*DMODEL];
__device__ float g_AO [M_ROWS*DMODEL];
__device__ float g_T0 [M_ROWS*DMODEL];
__device__ float g_X1 [M_ROWS*DMODEL];
__device__ float g_X1R[M_ROWS*DMODEL];
__device__ float g_H  [M_ROWS*DINNER];
__device__ float g_qr [M_ROWS*DMODEL];
__device__ float g_kr [M_ROWS*DMODEL];
__device__ float g_vr [M_ROWS*DMODEL];
__device__ float g_WQR[DMODEL*DMODEL];
__device__ float g_WKR[DMODEL*DMODEL];
__device__ float g_WVR[DMODEL*DMODEL];
__device__ float g_WFR[DMODEL*DMODEL];
__device__ float g_W1R[DMODEL*DINNER];
__device__ float g_W2R[DINNER*DMODEL];

__device__ __forceinline__ float tf32r(float x) {
    uint32_t u;
    asm("cvt.rna.tf32.f32 %0, %1;" : "=r"(u) : "f"(x));
    return __uint_as_float(u);
}

// fast exp on fma/alu pipes (no MUFU). valid for x <= ~0; deg-5, err ~2e-6.
__device__ __forceinline__ float fexp(float x) {
    float y = x * 1.4426950408889634f;
    float n = rintf(y);
    float f = y - n;
    float p = 1.3333558e-3f;
    p = fmaf(p, f, 9.6181291e-3f);
    p = fmaf(p, f, 5.5504109e-2f);
    p = fmaf(p, f, 2.4022651e-1f);
    p = fmaf(p, f, 6.9314718e-1f);
    p = fmaf(p, f, 1.0f);
    n = fmaxf(n, -126.f);
    float s = __int_as_float(((int)n + 127) << 23);
    return p * s;
}

#define MMA_TF32(ac, a0,a1,a2,a3, b0,b1)                                      \
    asm volatile(                                                             \
        "mma.sync.aligned.m16n8k8.row.col.f32.tf32.tf32.f32 "                 \
        "{%0,%1,%2,%3}, {%4,%5,%6,%7}, {%8,%9}, {%0,%1,%2,%3};"               \
        : "+f"(ac[0]), "+f"(ac[1]), "+f"(ac[2]), "+f"(ac[3])                  \
        : "r"(a0), "r"(a1), "r"(a2), "r"(a3), "r"(b0), "r"(b1))

__device__ __forceinline__ void cpa16(void* smem, const void* gmem) {
    uint32_t s = (uint32_t)__cvta_generic_to_shared(smem);
    asm volatile("cp.async.cg.shared.global [%0], [%1], 16;\n" :: "r"(s), "l"(gmem));
}
__device__ __forceinline__ void cpa_commit() {
    asm volatile("cp.async.commit_group;\n" ::);
}
template<int N>
__device__ __forceinline__ void cpa_wait() {
    asm volatile("cp.async.wait_group %0;\n" :: "n"(N));
}

// ---------------------------------------------------------------------------
// rna-round copy (float4)
// ---------------------------------------------------------------------------
__global__ void round_kernel(const float* __restrict__ X, float* __restrict__ Y, int n4)
{
    int i = blockIdx.x * blockDim.x + threadIdx.x;
    if (i < n4) {
        float4 v = ((const float4*)X)[i];
        float4 o;
        o.x = tf32r(v.x); o.y = tf32r(v.y); o.z = tf32r(v.z); o.w = tf32r(v.w);
        ((float4*)Y)[i] = o;
    }
}

// ---------------------------------------------------------------------------
// TF32 tensor-core GEMM (cp.async 4-stage). Inputs pre-rounded (rna).
// ---------------------------------------------------------------------------
#define A_STRIDE 20
#define B_STRIDE 136
#define STAGES 4

__global__ __launch_bounds__(256, 2)
void gemm_tf32(const float* __restrict__ A, const float* __restrict__ W,
               const float* __restrict__ bias, const float* __restrict__ res,
               float* __restrict__ C, int N, int K, int relu, int rnd)
{
    __shared__ __align__(16) float As[STAGES][128 * A_STRIDE];
    __shared__ __align__(16) float Bs[STAGES][16 * B_STRIDE];

    const int tid  = threadIdx.x;
    const int lane = tid & 31;
    const int warp = tid >> 5;
    const int wm = warp & 3, wn = warp >> 2;
    const int m0 = wm * 32, n0 = wn * 64;
    const int bm = blockIdx.y * 128, bn = blockIdx.x * 128;

    const int arow = tid >> 2, ac = (tid & 3) << 2;
    const int brow = tid >> 5, bc = (tid & 31) << 2;
    const float* ApA = A + (size_t)(bm + arow) * K + ac;
    const float* ApB = ApA + (size_t)64 * K;
    const float* WpA = W + (size_t)brow * N + bn + bc;
    const float* WpB = W + (size_t)(brow + 8) * N + bn + bc;

    const int NT = K >> 4;

    #pragma unroll
    for (int s = 0; s < STAGES - 1; s++) {
        const int k0g = s << 4;
        cpa16(&As[s][arow * A_STRIDE + ac],        ApA + k0g);
        cpa16(&As[s][(arow + 64) * A_STRIDE + ac], ApB + k0g);
        cpa16(&Bs[s][brow * B_STRIDE + bc],        WpA + (size_t)k0g * N);
        cpa16(&Bs[s][(brow + 8) * B_STRIDE + bc],  WpB + (size_t)k0g * N);
        cpa_commit();
    }
    cpa_wait<STAGES - 2>();
    __syncthreads();

    float acc[2][8][4];
    #pragma unroll
    for (int mt = 0; mt < 2; mt++)
        #pragma unroll
        for (int j = 0; j < 8; j++)
            #pragma unroll
            for (int e = 0; e < 4; e++) acc[mt][j][e] = 0.f;

    for (int kt = 0; kt < NT; kt++) {
        const int cur = kt & (STAGES - 1);
        const int ktn = kt + STAGES - 1;
        if (ktn < NT) {
            const int sn = ktn & (STAGES - 1);
            const int k0g = ktn << 4;
            cpa16(&As[sn][arow * A_STRIDE + ac],        ApA + k0g);
            cpa16(&As[sn][(arow + 64) * A_STRIDE + ac], ApB + k0g);
            cpa16(&Bs[sn][brow * B_STRIDE + bc],        WpA + (size_t)k0g * N);
            cpa16(&Bs[sn][(brow + 8) * B_STRIDE + bc],  WpB + (size_t)k0g * N);
        }
        cpa_commit();

        const float* as = As[cur];
        const float* bs = Bs[cur];
        const float* ap = as + (size_t)(m0 + (lane >> 2)) * A_STRIDE + (lane & 3);

        #pragma unroll
        for (int ks = 0; ks < 2; ks++) {
            const int k0 = ks << 3;
            uint32_t afr[2][4];
            #pragma unroll
            for (int mt = 0; mt < 2; mt++) {
                afr[mt][0] = __float_as_uint(ap[(mt * 16    ) * A_STRIDE + k0    ]);
                afr[mt][1] = __float_as_uint(ap[(mt * 16 + 8) * A_STRIDE + k0    ]);
                afr[mt][2] = __float_as_uint(ap[(mt * 16    ) * A_STRIDE + k0 + 4]);
                afr[mt][3] = __float_as_uint(ap[(mt * 16 + 8) * A_STRIDE + k0 + 4]);
            }
            const float* bp = bs + (k0 + (lane & 3)) * B_STRIDE + n0 + (lane >> 2);
            #pragma unroll
            for (int j = 0; j < 8; j++) {
                uint32_t b0 = __float_as_uint(bp[j * 8]);
                uint32_t b1 = __float_as_uint(bp[j * 8 + 4 * B_STRIDE]);
                #pragma unroll
                for (int mt = 0; mt < 2; mt++) {
                    MMA_TF32(acc[mt][j], afr[mt][0], afr[mt][1], afr[mt][2], afr[mt][3], b0, b1);
                }
            }
        }

        cpa_wait<STAGES - 2>();
        __syncthreads();
    }

    const int r_lane = lane >> 2;
    const int c_lane = (lane & 3) << 1;
    #pragma unroll
    for (int mt = 0; mt < 2; mt++) {
        const int row0 = bm + m0 + mt * 16 + r_lane;
        #pragma unroll
        for (int j = 0; j < 8; j++) {
            const int col = bn + n0 + j * 8 + c_lane;
            float2 bb = *(const float2*)(bias + col);
            float2 v0, v1;
            v0.x = acc[mt][j][0] + bb.x; v0.y = acc[mt][j][1] + bb.y;
            v1.x = acc[mt][j][2] + bb.x; v1.y = acc[mt][j][3] + bb.y;
            if (res) {
                float2 r0 = *(const float2*)(res + (size_t)row0 * N + col);
                float2 r1 = *(const float2*)(res + (size_t)(row0 + 8) * N + col);
                v0.x += r0.x; v0.y += r0.y;
                v1.x += r1.x; v1.y += r1.y;
            }
            if (relu) {
                v0.x = fmaxf(v0.x, 0.f); v0.y = fmaxf(v0.y, 0.f);
                v1.x = fmaxf(v1.x, 0.f); v1.y = fmaxf(v1.y, 0.f);
            }
            if (rnd) {
                v0.x = tf32r(v0.x); v0.y = tf32r(v0.y);
                v1.x = tf32r(v1.x); v1.y = tf32r(v1.y);
            }
            *(float2*)(C + (size_t)row0 * N + col) = v0;
            *(float2*)(C + (size_t)(row0 + 8) * N + col) = v1;
        }
    }
}

// ---------------------------------------------------------------------------
// MMA relative attention. Block = (b, h, 64-q tile), 256 threads / 8 warps.
// Warp w: rows m0=(w&3)*16, cols n0h=(w>>2)*32 (4 n8-tiles).
// exp on fma pipe (fexp). P rounded tf32 consistently (Ps, lrow, Tac).
// ---------------------------------------------------------------------------
#define ATTN_SMEM (22208 * 4)

__global__ __launch_bounds__(256)
void attn_mma(const float* __restrict__ Q, const float* __restrict__ Km,
              const float* __restrict__ Vm, const float* __restrict__ relk,
              const float* __restrict__ relv, float* __restrict__ O)
{
    extern __shared__ float sm[];
    float* Qs  = sm;            // [64][68]
    float* Ks  = sm + 4352;     // [64][68]
    float* Vs  = sm + 8704;     // [64][72]
    float* Ps  = sm + 13312;    // [64][68]
    float* Sq  = sm + 17664;    // [64][33]
    float* Tac = sm + 19776;    // [64][33]
    float* mrow= sm + 21888;    // [64]
    float* lrow= sm + 21952;    // [64]
    float* crow= sm + 22016;    // [64]
    float* red = sm + 22080;    // [64][2]
    float* Rk  = Ps;            // overlay pre-loop
    float* Rv  = Ks;            // overlay post-loop

    const int tid  = threadIdx.x;
    const int lane = tid & 31, warp = tid >> 5;
    const int m0   = (warp & 3) * 16;
    const int n0h  = (warp >> 2) * 32;
    const int wh   = warp >> 2;
    const int lr = lane >> 2, lc = lane & 3;
    const int b = blockIdx.z, h = blockIdx.y;
    const int q0 = blockIdx.x << 6;

    for (int i = tid; i < 1024; i += 256) {
        int r = i >> 4, c = (i & 15) << 2;
        float4 v = *(const float4*)(Q + (size_t)(b*LSEQ + q0 + r)*DMODEL + h*64 + c);
        Qs[r*68+c]   = tf32r(v.x); Qs[r*68+c+1] = tf32r(v.y);
        Qs[r*68+c+2] = tf32r(v.z); Qs[r*68+c+3] = tf32r(v.w);
    }
    for (int i = tid; i < 2112; i += 256) { Rk[i] = relk[i]; Tac[i] = 0.f; }
    if (tid < 64) { mrow[tid] = -1e30f; lrow[tid] = 0.f; }
    __syncthreads();

    // Sq[q][r] = (Qh[q] . rel_k[r]) / 8
    for (int i = tid; i < 2112; i += 256) {
        int qq = i / 33, r = i - qq*33;
        float s = 0.f;
        #pragma unroll 8
        for (int d = 0; d < 64; d++) s += Qs[qq*68 + d] * Rk[r*64 + d];
        Sq[i] = s * 0.125f;
    }

    float oacc[4][4];
    #pragma unroll
    for (int j = 0; j < 4; j++)
        #pragma unroll
        for (int e = 0; e < 4; e++) oacc[j][e] = 0.f;

    const int rowA = m0 + lr, rowB = rowA + 8;
    const int qgA = q0 + rowA, qgB = q0 + rowB;

    for (int kt = 0; kt < 16; kt++) {
        const int kbase = kt << 6;
        __syncthreads();
        for (int i = tid; i < 1024; i += 256) {
            int r = i >> 4, c = (i & 15) << 2;
            size_t go = (size_t)(b*LSEQ + kbase + r)*DMODEL + h*64 + c;
            float4 kv = *(const float4*)(Km + go);
            float4 vv = *(const float4*)(Vm + go);
            Ks[r*68+c]   = tf32r(kv.x); Ks[r*68+c+1] = tf32r(kv.y);
            Ks[r*68+c+2] = tf32r(kv.z); Ks[r*68+c+3] = tf32r(kv.w);
            Vs[r*72+c]   = tf32r(vv.x); Vs[r*72+c+1] = tf32r(vv.y);
            Vs[r*72+c+2] = tf32r(vv.z); Vs[r*72+c+3] = tf32r(vv.w);
        }
        __syncthreads();

        // --- S = Q @ K^T ---
        float sfr[4][4];
        #pragma unroll
        for (int j = 0; j < 4; j++)
            #pragma unroll
            for (int e = 0; e < 4; e++) sfr[j][e] = 0.f;

        const float* apq = Qs + (size_t)(m0 + lr)*68 + lc;
        #pragma unroll
        for (int ks = 0; ks < 8; ks++) {
            const int k0 = ks << 3;
            uint32_t a0 = __float_as_uint(apq[k0]);
            uint32_t a1 = __float_as_uint(apq[8*68 + k0]);
            uint32_t a2 = __float_as_uint(apq[k0 + 4]);
            uint32_t a3 = __float_as_uint(apq[8*68 + k0 + 4]);
            #pragma unroll
            for (int j = 0; j < 4; j++) {
                const float* bp = Ks + (size_t)(n0h + 8*j + lr)*68 + k0 + lc;
                uint32_t b0 = __float_as_uint(bp[0]);
                uint32_t b1 = __float_as_uint(bp[4]);
                MMA_TF32(sfr[j], a0, a1, a2, a3, b0, b1);
            }
        }

        // --- bias + row max ---
        float rmA = -1e30f, rmB = -1e30f;
        #pragma unroll
        for (int j = 0; j < 4; j++) {
            #pragma unroll
            for (int e = 0; e < 4; e++) {
                int col = n0h + 8*j + 2*lc + (e & 1);
                int kg = kbase + col;
                int row = (e < 2) ? rowA : rowB;
                int qg  = (e < 2) ? qgA : qgB;
                int d = kg - qg;
                int rb = d < -16 ? 0 : (d > 16 ? 32 : d + 16);
                float s = fmaf(sfr[j][e], 0.125f, Sq[row*33 + rb]);
                sfr[j][e] = s;
                if (e < 2) rmA = fmaxf(rmA, s); else rmB = fmaxf(rmB, s);
            }
        }
        rmA = fmaxf(rmA, __shfl_xor_sync(0xffffffffu, rmA, 1));
        rmA = fmaxf(rmA, __shfl_xor_sync(0xffffffffu, rmA, 2));
        rmB = fmaxf(rmB, __shfl_xor_sync(0xffffffffu, rmB, 1));
        rmB = fmaxf(rmB, __shfl_xor_sync(0xffffffffu, rmB, 2));
        if (lc == 0) { red[rowA*2 + wh] = rmA; red[rowB*2 + wh] = rmB; }
        __syncthreads();

        if (tid < 64) {
            float mo = mrow[tid];
            float mn = fmaxf(mo, fmaxf(red[tid*2], red[tid*2+1]));
            float c = fexp(mo - mn);
            mrow[tid] = mn; crow[tid] = c; lrow[tid] *= c;
            #pragma unroll
            for (int r = 0; r < 33; r++) Tac[tid*33 + r] *= c;
        }
        __syncthreads();

        // --- P = exp(S - m); store + bucket accumulate + row sums ---
        const float mA = mrow[rowA], mB = mrow[rowB];
        float rsA = 0.f, rsB = 0.f, e0A = 0.f, e32A = 0.f, e0B = 0.f, e32B = 0.f;
        #pragma unroll
        for (int j = 0; j < 4; j++) {
            #pragma unroll
            for (int e = 0; e < 4; e++) {
                int col = n0h + 8*j + 2*lc + (e & 1);
                int kg = kbase + col;
                if (e < 2) {
                    float p = tf32r(fexp(sfr[j][e] - mA));
                    Ps[rowA*68 + col] = p;
                    rsA += p;
                    int d = kg - qgA;
                    if (d <= -16) e0A += p; else if (d >= 16) e32A += p;
                    else Tac[rowA*33 + d + 16] += p;
                } else {
                    float p = tf32r(fexp(sfr[j][e] - mB));
                    Ps[rowB*68 + col] = p;
                    rsB += p;
                    int d = kg - qgB;
                    if (d <= -16) e0B += p; else if (d >= 16) e32B += p;
                    else Tac[rowB*33 + d + 16] += p;
                }
            }
        }
        rsA  += __shfl_xor_sync(0xffffffffu, rsA, 1);  rsA  += __shfl_xor_sync(0xffffffffu, rsA, 2);
        rsB  += __shfl_xor_sync(0xffffffffu, rsB, 1);  rsB  += __shfl_xor_sync(0xffffffffu, rsB, 2);
        e0A  += __shfl_xor_sync(0xffffffffu, e0A, 1);  e0A  += __shfl_xor_sync(0xffffffffu, e0A, 2);
        e32A += __shfl_xor_sync(0xffffffffu, e32A, 1); e32A += __shfl_xor_sync(0xffffffffu, e32A, 2);
        e0B  += __shfl_xor_sync(0xffffffffu, e0B, 1);  e0B  += __shfl_xor_sync(0xffffffffu, e0B, 2);
        e32B += __shfl_xor_sync(0xffffffffu, e32B, 1); e32B += __shfl_xor_sync(0xffffffffu, e32B, 2);
        if (lc == 0) {
            red[rowA*2 + wh] = rsA;
            red[rowB*2 + wh] = rsB;
            if (e0A  != 0.f) atomicAdd(&Tac[rowA*33],      e0A);
            if (e32A != 0.f) atomicAdd(&Tac[rowA*33 + 32], e32A);
            if (e0B  != 0.f) atomicAdd(&Tac[rowB*33],      e0B);
            if (e32B != 0.f) atomicAdd(&Tac[rowB*33 + 32], e32B);
        }
        // rescale O accumulators
        {
            float cA = crow[rowA], cB = crow[rowB];
            #pragma unroll
            for (int j = 0; j < 4; j++) {
                oacc[j][0] *= cA; oacc[j][1] *= cA;
                oacc[j][2] *= cB; oacc[j][3] *= cB;
            }
        }
        __syncthreads();

        // --- O += P @ V ---
        const float* app = Ps + (size_t)(m0 + lr)*68 + lc;
        #pragma unroll
        for (int ks = 0; ks < 8; ks++) {
            const int k0 = ks << 3;
            uint32_t a0 = __float_as_uint(app[k0]);
            uint32_t a1 = __float_as_uint(app[8*68 + k0]);
            uint32_t a2 = __float_as_uint(app[k0 + 4]);
            uint32_t a3 = __float_as_uint(app[8*68 + k0 + 4]);
            #pragma unroll
            for (int j = 0; j < 4; j++) {
                const float* bp = Vs + (size_t)(k0 + lc)*72 + n0h + 8*j + lr;
                uint32_t b0 = __float_as_uint(bp[0]);
                uint32_t b1 = __float_as_uint(bp[4*72]);
                MMA_TF32(oacc[j], a0, a1, a2, a3, b0, b1);
            }
        }
        if (tid < 64) lrow[tid] += red[tid*2] + red[tid*2+1];
    }

    __syncthreads();
    for (int i = tid; i < 2112; i += 256) Rv[i] = relv[i];
    __syncthreads();

    // epilogue: O = (oacc + Tac @ rel_v) / l, rounded for the fc GEMM
    float acc2[4][4];
    #pragma unroll
    for (int j = 0; j < 4; j++)
        #pragma unroll
        for (int e = 0; e < 4; e++) acc2[j][e] = 0.f;
    for (int r = 0; r < 33; r++) {
        float ta = Tac[rowA*33 + r], tb = Tac[rowB*33 + r];
        #pragma unroll
        for (int j = 0; j < 4; j++) {
            float rv0 = Rv[r*64 + n0h + 8*j + 2*lc];
            float rv1 = Rv[r*64 + n0h + 8*j + 2*lc + 1];
            acc2[j][0] = fmaf(ta, rv0, acc2[j][0]);
            acc2[j][1] = fmaf(ta, rv1, acc2[j][1]);
            acc2[j][2] = fmaf(tb, rv0, acc2[j][2]);
            acc2[j][3] = fmaf(tb, rv1, acc2[j][3]);
        }
    }
    float ilA = 1.f / lrow[rowA], ilB = 1.f / lrow[rowB];
    #pragma unroll
    for (int j = 0; j < 4; j++) {
        int col = n0h + 8*j + 2*lc;
        float2 o0, o1;
        o0.x = tf32r((oacc[j][0] + acc2[j][0]) * ilA);
        o0.y = tf32r((oacc[j][1] + acc2[j][1]) * ilA);
        o1.x = tf32r((oacc[j][2] + acc2[j][2]) * ilB);
        o1.y = tf32r((oacc[j][3] + acc2[j][3]) * ilB);
        *(float2*)(O + (size_t)(b*LSEQ + q0 + rowA)*DMODEL + h*64 + col) = o0;
        *(float2*)(O + (size_t)(b*LSEQ + q0 + rowB)*DMODEL + h*64 + col) = o1;
    }
}

// ---------------------------------------------------------------------------
// LayerNorm; optional rounded second output (for next GEMM's A operand)
// ---------------------------------------------------------------------------
__global__ void ln_kernel(const float* __restrict__ X, const float* __restrict__ g,
                          const float* __restrict__ bta, float* __restrict__ Y,
                          float* __restrict__ Yr)
{
    __shared__ float rs[18];
    const int row = blockIdx.x, tid = threadIdx.x;
    float4 v = ((const float4*)(X + (size_t)row * 1024))[tid];
    float s  = v.x + v.y + v.z + v.w;
    float s2 = v.x*v.x + v.y*v.y + v.z*v.z + v.w*v.w;
    #pragma unroll
    for (int o = 16; o > 0; o >>= 1) {
        s  += __shfl_down_sync(0xffffffffu, s, o);
        s2 += __shfl_down_sync(0xffffffffu, s2, o);
    }
    int wid = tid >> 5;
    if ((tid & 31) == 0) { rs[wid] = s; rs[8 + wid] = s2; }
    __syncthreads();
    if (tid == 0) {
        float ts = 0.f, ts2 = 0.f;
        for (int w = 0; w < 8; w++) { ts += rs[w]; ts2 += rs[8 + w]; }
        float mu = ts * (1.f / 1024.f);
        float var = ts2 * (1.f / 1024.f) - mu * mu;
        rs[16] = mu;
        rs[17] = rsqrtf(var + 1e-6f);
    }
    __syncthreads();
    float mu = rs[16], rstd = rs[17];
    float4 gg = ((const float4*)g)[tid];
    float4 bb = ((const float4*)bta)[tid];
    float4 o;
    o.x = (v.x - mu) * rstd * gg.x + bb.x;
    o.y = (v.y - mu) * rstd * gg.y + bb.y;
    o.z = (v.z - mu) * rstd * gg.z + bb.z;
    o.w = (v.w - mu) * rstd * gg.w + bb.w;
    ((float4*)(Y + (size_t)row * 1024))[tid] = o;
    if (Yr) {
        float4 r;
        r.x = tf32r(o.x); r.y = tf32r(o.y); r.z = tf32r(o.z); r.w = tf32r(o.w);
        ((float4*)(Yr + (size_t)row * 1024))[tid] = r;
    }
}

// ---------------------------------------------------------------------------
extern "C" void kernel_launch(void* const* d_in, const int* in_sizes, int n_in,
                              void* d_out, int out_size)
{
    const float* q    = (const float*)d_in[0];
    const float* k    = (const float*)d_in[1];
    const float* v    = (const float*)d_in[2];
    const float* wq   = (const float*)d_in[3];
    const float* bq   = (const float*)d_in[4];
    const float* wk   = (const float*)d_in[5];
    const float* bk   = (const float*)d_in[6];
    const float* wv   = (const float*)d_in[7];
    const float* bv   = (const float*)d_in[8];
    const float* wfc  = (const float*)d_in[9];
    const float* bfc  = (const float*)d_in[10];
    const float* w1   = (const float*)d_in[11];
    const float* b1   = (const float*)d_in[12];
    const float* w2   = (const float*)d_in[13];
    const float* b2   = (const float*)d_in[14];
    const float* lng  = (const float*)d_in[15];
    const float* lnb  = (const float*)d_in[16];
    const float* relk = (const float*)d_in[17];
    const float* relv = (const float*)d_in[18];
    float* out = (float*)d_out;

    float *Qp, *Kp, *Vp, *AOp, *T0p, *X1p, *X1Rp, *Hp;
    float *qr, *kr, *vr, *wqr, *wkr, *wvr, *wfr, *w1r, *w2r;
    cudaGetSymbolAddress((void**)&Qp,   g_Q);
    cudaGetSymbolAddress((void**)&Kp,   g_K);
    cudaGetSymbolAddress((void**)&Vp,   g_V);
    cudaGetSymbolAddress((void**)&AOp,  g_AO);
    cudaGetSymbolAddress((void**)&T0p,  g_T0);
    cudaGetSymbolAddress((void**)&X1p,  g_X1);
    cudaGetSymbolAddress((void**)&X1Rp, g_X1R);
    cudaGetSymbolAddress((void**)&Hp,   g_H);
    cudaGetSymbolAddress((void**)&qr,   g_qr);
    cudaGetSymbolAddress((void**)&kr,   g_kr);
    cudaGetSymbolAddress((void**)&vr,   g_vr);
    cudaGetSymbolAddress((void**)&wqr,  g_WQR);
    cudaGetSymbolAddress((void**)&wkr,  g_WKR);
    cudaGetSymbolAddress((void**)&wvr,  g_WVR);
    cudaGetSymbolAddress((void**)&wfr,  g_WFR);
    cudaGetSymbolAddress((void**)&w1r,  g_W1R);
    cudaGetSymbolAddress((void**)&w2r,  g_W2R);

    cudaFuncSetAttribute(attn_mma, cudaFuncAttributeMaxDynamicSharedMemorySize, ATTN_SMEM);

    // rna-round weights + raw inputs (removes truncation error at MMA operands)
    const int MM = DMODEL * DMODEL / 4;
    const int MI = DINNER * DMODEL / 4;
    const int MR = M_ROWS * DMODEL / 4;
    round_kernel<<<(MM + 255) / 256, 256>>>(wq,  wqr, MM);
    round_kernel<<<(MM + 255) / 256, 256>>>(wk,  wkr, MM);
    round_kernel<<<(MM + 255) / 256, 256>>>(wv,  wvr, MM);
    round_kernel<<<(MM + 255) / 256, 256>>>(wfc, wfr, MM);
    round_kernel<<<(MI + 255) / 256, 256>>>(w1,  w1r, MI);
    round_kernel<<<(MI + 255) / 256, 256>>>(w2,  w2r, MI);
    round_kernel<<<(MR + 255) / 256, 256>>>(q,   qr,  MR);
    round_kernel<<<(MR + 255) / 256, 256>>>(k,   kr,  MR);
    round_kernel<<<(MR + 255) / 256, 256>>>(v,   vr,  MR);

    dim3 blk(256);
    dim3 g1024(1024 / 128, 8192 / 128);
    dim3 g4096(4096 / 128, 8192 / 128);

    gemm_tf32<<<g1024, blk>>>(qr, wqr, bq, nullptr, Qp, 1024, 1024, 0, 0);
    gemm_tf32<<<g1024, blk>>>(kr, wkr, bk, nullptr, Kp, 1024, 1024, 0, 0);
    gemm_tf32<<<g1024, blk>>>(vr, wvr, bv, nullptr, Vp, 1024, 1024, 0, 0);

    attn_mma<<<dim3(16, NHEAD, 8), blk, ATTN_SMEM>>>(Qp, Kp, Vp, relk, relv, AOp);

    gemm_tf32<<<g1024, blk>>>(AOp, wfr, bfc, q, T0p, 1024, 1024, 0, 0);
    ln_kernel<<<8192, 256>>>(T0p, lng, lnb, X1p, X1Rp);

    gemm_tf32<<<g4096, blk>>>(X1Rp, w1r, b1, nullptr, Hp, 4096, 1024, 1, 1);
    gemm_tf32<<<g1024, blk>>>(Hp, w2r, b2, X1p, T0p, 1024, 4096, 0, 0);
    ln_kernel<<<8192, 256>>>(T0p, lng, lnb, out, nullptr);
}